// round 1
// baseline (speedup 1.0000x reference)
#include <cuda_runtime.h>
#include <cuda_bf16.h>

// GCN: out = relu( D_in^{-1/2} * A * D_out^{-1/2} * (X W) + b )
// N=100000 nodes, E=1600000 edges, IN=64, HID=32.
// Inputs (metadata order): features [N,64] f32, src [E] i32, dst [E] i32,
//                          W [64,32] f32, b [32] f32.
// Output: [N,32] f32.

#define N_NODES 100000
#define N_EDGES 1600000
#define IN_DIM  64
#define HID_DIM 32

// Scratch (no cudaMalloc allowed)
__device__ float g_deg_out[N_NODES];
__device__ float g_deg_in[N_NODES];
__device__ float g_h[N_NODES * HID_DIM];

// ---------------------------------------------------------------------------
// Zero scratch + output
__global__ void k_zero(float* __restrict__ out, int out_n) {
    int i = blockIdx.x * blockDim.x + threadIdx.x;
    int stride = gridDim.x * blockDim.x;
    for (int j = i; j < N_NODES; j += stride) {
        g_deg_out[j] = 0.0f;
        g_deg_in[j]  = 0.0f;
    }
    for (int j = i; j < out_n; j += stride) {
        out[j] = 0.0f;
    }
}

// ---------------------------------------------------------------------------
// Degree counts: one thread per edge, two atomics
__global__ void k_degrees(const int* __restrict__ src,
                          const int* __restrict__ dst) {
    int e = blockIdx.x * blockDim.x + threadIdx.x;
    if (e < N_EDGES) {
        atomicAdd(&g_deg_out[src[e]], 1.0f);
        atomicAdd(&g_deg_in[dst[e]],  1.0f);
    }
}

// ---------------------------------------------------------------------------
// h = (X @ W) * norm_src.  Block: 256 threads = 8 nodes x 32 cols.
// W tile (64x32 f32 = 8KB) + X tile (8x64 f32 = 2KB) in smem.
__global__ __launch_bounds__(256) void k_gemm(const float* __restrict__ X,
                                              const float* __restrict__ W) {
    __shared__ float sW[IN_DIM * HID_DIM];   // [k][col]
    __shared__ float sX[8 * IN_DIM];         // [node_local][k]

    int tid = threadIdx.x;
    int node_base = blockIdx.x * 8;

    #pragma unroll
    for (int i = tid; i < IN_DIM * HID_DIM; i += 256) sW[i] = W[i];

    for (int i = tid; i < 8 * IN_DIM; i += 256) {
        int node = node_base + (i >> 6);
        sX[i] = (node < N_NODES) ? X[node * IN_DIM + (i & 63)] : 0.0f;
    }
    __syncthreads();

    int node_local = tid >> 5;          // 0..7
    int col = tid & 31;                 // 0..31
    int node = node_base + node_local;
    if (node >= N_NODES) return;

    float acc = 0.0f;
    #pragma unroll
    for (int k = 0; k < IN_DIM; k++) {
        acc += sX[node_local * IN_DIM + k] * sW[k * HID_DIM + col];
    }
    float d = g_deg_out[node];
    float norm = rsqrtf(fmaxf(d, 1.0f));
    g_h[node * HID_DIM + col] = acc * norm;
}

// ---------------------------------------------------------------------------
// Edge scatter: one warp per edge; lane = column.
// Coalesced 128B read of h[src] row; 32 atomicAdds into out[dst] row.
__global__ __launch_bounds__(256) void k_scatter(const int* __restrict__ src,
                                                 const int* __restrict__ dst,
                                                 float* __restrict__ out) {
    int gtid = blockIdx.x * blockDim.x + threadIdx.x;
    int e = gtid >> 5;
    int lane = gtid & 31;
    if (e >= N_EDGES) return;

    int s = __ldg(&src[e]);
    int d = __ldg(&dst[e]);
    float v = __ldg(&g_h[s * HID_DIM + lane]);
    atomicAdd(&out[d * HID_DIM + lane], v);
}

// ---------------------------------------------------------------------------
// Finalize: out = relu(out * norm_dst + b)
__global__ __launch_bounds__(256) void k_final(float* __restrict__ out,
                                               const float* __restrict__ b) {
    int i = blockIdx.x * blockDim.x + threadIdx.x;
    if (i >= N_NODES * HID_DIM) return;
    int node = i >> 5;      // HID_DIM == 32
    int col = i & 31;
    float deg = g_deg_in[node];
    float norm = rsqrtf(fmaxf(deg, 1.0f));
    float v = out[i] * norm + b[col];
    out[i] = fmaxf(v, 0.0f);
}

// ---------------------------------------------------------------------------
extern "C" void kernel_launch(void* const* d_in, const int* in_sizes, int n_in,
                              void* d_out, int out_size) {
    const float* features = (const float*)d_in[0];
    const int*   src      = (const int*)d_in[1];
    const int*   dst      = (const int*)d_in[2];
    const float* W        = (const float*)d_in[3];
    const float* b        = (const float*)d_in[4];
    float* out = (float*)d_out;

    k_zero<<<1024, 256>>>(out, out_size);

    k_degrees<<<(N_EDGES + 255) / 256, 256>>>(src, dst);

    k_gemm<<<(N_NODES + 7) / 8, 256>>>(features, W);

    long long scatter_threads = (long long)N_EDGES * 32;
    int scatter_blocks = (int)((scatter_threads + 255) / 256);
    k_scatter<<<scatter_blocks, 256>>>(src, dst, out);

    k_final<<<(N_NODES * HID_DIM + 255) / 256, 256>>>(out, b);
}

// round 3
// speedup vs baseline: 1.6277x; 1.6277x over previous
#include <cuda_runtime.h>
#include <cuda_bf16.h>

// GCN: out = relu( D_in^{-1/2} * A * D_out^{-1/2} * (X W) + b )
// N=100000 nodes, E=1600000 edges, IN=64, HID=32.
// Inputs (metadata order): features [N,64] f32, src [E] i32, dst [E] i32,
//                          W [64,32] f32, b [32] f32.
// Output: [N,32] f32.

#define N_NODES 100000
#define N_EDGES 1600000
#define IN_DIM  64
#define HID_DIM 32

// Scratch (no cudaMalloc allowed)
__device__ float g_deg_out[N_NODES];
__device__ float g_deg_in[N_NODES];
__device__ float g_h[N_NODES * HID_DIM];

// ---------------------------------------------------------------------------
// Zero scratch + output
__global__ void k_zero(float* __restrict__ out, int out_n) {
    int i = blockIdx.x * blockDim.x + threadIdx.x;
    int stride = gridDim.x * blockDim.x;
    for (int j = i; j < N_NODES; j += stride) {
        g_deg_out[j] = 0.0f;
        g_deg_in[j]  = 0.0f;
    }
    float4 z = make_float4(0.f, 0.f, 0.f, 0.f);
    float4* out4 = (float4*)out;
    int n4 = out_n >> 2;
    for (int j = i; j < n4; j += stride) {
        out4[j] = z;
    }
}

// ---------------------------------------------------------------------------
// Degree counts: one thread per edge, two no-return reductions
__global__ void k_degrees(const int* __restrict__ src,
                          const int* __restrict__ dst) {
    int e = blockIdx.x * blockDim.x + threadIdx.x;
    if (e < N_EDGES) {
        atomicAdd(&g_deg_out[src[e]], 1.0f);   // ptxas -> REDG (result unused)
        atomicAdd(&g_deg_in[dst[e]],  1.0f);
    }
}

// ---------------------------------------------------------------------------
// h = (X @ W) * norm_src.  Block: 256 threads = 8 nodes x 32 cols.
__global__ __launch_bounds__(256) void k_gemm(const float* __restrict__ X,
                                              const float* __restrict__ W) {
    __shared__ float sW[IN_DIM * HID_DIM];   // [k][col]
    __shared__ float sX[8 * IN_DIM];         // [node_local][k]

    int tid = threadIdx.x;
    int node_base = blockIdx.x * 8;

    #pragma unroll
    for (int i = tid; i < IN_DIM * HID_DIM; i += 256) sW[i] = W[i];

    for (int i = tid; i < 8 * IN_DIM; i += 256) {
        int node = node_base + (i >> 6);
        sX[i] = (node < N_NODES) ? X[node * IN_DIM + (i & 63)] : 0.0f;
    }
    __syncthreads();

    int node_local = tid >> 5;          // 0..7
    int col = tid & 31;                 // 0..31
    int node = node_base + node_local;
    if (node >= N_NODES) return;

    float acc = 0.0f;
    #pragma unroll
    for (int k = 0; k < IN_DIM; k++) {
        acc += sX[node_local * IN_DIM + k] * sW[k * HID_DIM + col];
    }
    float d = g_deg_out[node];
    float norm = rsqrtf(fmaxf(d, 1.0f));
    g_h[node * HID_DIM + col] = acc * norm;
}

// ---------------------------------------------------------------------------
// Edge scatter, vectorized: 8 lanes per edge, each lane owns one float4
// (16B) of the 32-float row. Per edge: 8x red.global.add.v4.f32 instead of
// 32 scalar atomics -> 4x fewer LTS address transactions.
__global__ __launch_bounds__(256) void k_scatter(const int* __restrict__ src,
                                                 const int* __restrict__ dst,
                                                 float* __restrict__ out) {
    int gtid = blockIdx.x * blockDim.x + threadIdx.x;
    int e = gtid >> 3;                  // 8 threads per edge
    if (e >= N_EDGES) return;
    int sub = gtid & 7;                 // which float4 of the row (0..7)

    int s = __ldg(&src[e]);
    int d = __ldg(&dst[e]);

    const float4* hrow = (const float4*)(&g_h[s * HID_DIM]);
    float4 v = __ldg(&hrow[sub]);

    float* p = &out[d * HID_DIM + (sub << 2)];
    asm volatile("red.global.add.v4.f32 [%0], {%1, %2, %3, %4};"
                 :: "l"(p), "f"(v.x), "f"(v.y), "f"(v.z), "f"(v.w)
                 : "memory");
}

// ---------------------------------------------------------------------------
// Finalize: out = relu(out * norm_dst + b)
__global__ __launch_bounds__(256) void k_final(float* __restrict__ out,
                                               const float* __restrict__ b) {
    int i = blockIdx.x * blockDim.x + threadIdx.x;
    if (i >= N_NODES * HID_DIM) return;
    int node = i >> 5;      // HID_DIM == 32
    int col = i & 31;
    float deg = g_deg_in[node];
    float norm = rsqrtf(fmaxf(deg, 1.0f));
    float v = out[i] * norm + b[col];
    out[i] = fmaxf(v, 0.0f);
}

// ---------------------------------------------------------------------------
extern "C" void kernel_launch(void* const* d_in, const int* in_sizes, int n_in,
                              void* d_out, int out_size) {
    const float* features = (const float*)d_in[0];
    const int*   src      = (const int*)d_in[1];
    const int*   dst      = (const int*)d_in[2];
    const float* W        = (const float*)d_in[3];
    const float* b        = (const float*)d_in[4];
    float* out = (float*)d_out;

    k_zero<<<1024, 256>>>(out, out_size);

    k_degrees<<<(N_EDGES + 255) / 256, 256>>>(src, dst);

    k_gemm<<<(N_NODES + 7) / 8, 256>>>(features, W);

    long long scatter_threads = (long long)N_EDGES * 8;
    int scatter_blocks = (int)((scatter_threads + 255) / 256);
    k_scatter<<<scatter_blocks, 256>>>(src, dst, out);

    k_final<<<(N_NODES * HID_DIM + 255) / 256, 256>>>(out, b);
}

// round 5
// speedup vs baseline: 1.8637x; 1.1450x over previous
#include <cuda_runtime.h>
#include <cuda_bf16.h>

// GCN: out = relu( D_in^{-1/2} * A * D_out^{-1/2} * (X W) + b )
// N=100000 nodes, E=1600000 edges, IN=64, HID=32.
// Inputs: features [N,64] f32, src [E] i32, dst [E] i32, W [64,32] f32, b [32] f32.
// Output: [N,32] f32.
//
// Pipeline: zero -> degrees(histograms) -> gemm(XW*norm_src) ->
//           scanA/B/C (offsets from deg_in) -> bucket (counting sort srcs by dst)
//           -> aggregate (warp per node, pull + norm_dst + bias + relu).

#define N_NODES 100000
#define N_EDGES 1600000
#define IN_DIM  64
#define HID_DIM 32

#define SCAN_CHUNK 512
#define SCAN_NBLK  ((N_NODES + SCAN_CHUNK - 1) / SCAN_CHUNK)   // 196

// Scratch (no cudaMalloc allowed)
__device__ int   g_deg_out[N_NODES];
__device__ int   g_deg_in[N_NODES];
__device__ float g_h[N_NODES * HID_DIM];
__device__ int   g_off[N_NODES];          // exclusive offsets by dst
__device__ int   g_cursor[N_NODES];       // bucket-fill cursors
__device__ int   g_srclist[N_EDGES];      // src ids grouped by dst
__device__ int   g_part[SCAN_NBLK];       // scan partials

// ---------------------------------------------------------------------------
__global__ void k_zero() {
    int i = blockIdx.x * blockDim.x + threadIdx.x;
    int stride = gridDim.x * blockDim.x;
    for (int j = i; j < N_NODES; j += stride) {
        g_deg_out[j] = 0;
        g_deg_in[j]  = 0;
    }
}

// ---------------------------------------------------------------------------
__global__ void k_degrees(const int* __restrict__ src,
                          const int* __restrict__ dst) {
    int e = blockIdx.x * blockDim.x + threadIdx.x;
    if (e < N_EDGES) {
        atomicAdd(&g_deg_out[src[e]], 1);   // no-return -> REDG
        atomicAdd(&g_deg_in[dst[e]],  1);
    }
}

// ---------------------------------------------------------------------------
// h = (X @ W) * norm_src.  Block: 256 threads, 64 nodes per block.
// Thread = (colgrp 0..7) x (nodepair 0..31): computes 2 nodes x 4 cols.
// float4 smem loads: 6 LDS.128 per 32 FFMA (smem-BW no longer binding).
__device__ __forceinline__ void fma4(float4& acc, float s, const float4& c) {
    acc.x += s * c.x;
    acc.y += s * c.y;
    acc.z += s * c.z;
    acc.w += s * c.w;
}

__global__ __launch_bounds__(256) void k_gemm(const float* __restrict__ X,
                                              const float* __restrict__ W) {
    __shared__ float sX[64 * IN_DIM];        // [node_local][k]  16KB
    __shared__ float sW[IN_DIM * HID_DIM];   // [k][col]          8KB

    int tid = threadIdx.x;
    int base = blockIdx.x * 64;

    // W: 2048 floats = 512 float4
    const float4* W4 = (const float4*)W;
    float4* sW4 = (float4*)sW;
    #pragma unroll
    for (int i = tid; i < 512; i += 256) sW4[i] = W4[i];

    // X tile: 64 nodes x 64 f32 = 1024 float4, coalesced
    const float4* X4 = (const float4*)X;
    float4* sX4 = (float4*)sX;
    float4 z = make_float4(0.f, 0.f, 0.f, 0.f);
    #pragma unroll
    for (int i = tid; i < 1024; i += 256) {
        int node = base + (i >> 4);
        sX4[i] = (node < N_NODES) ? X4[node * 16 + (i & 15)] : z;
    }
    __syncthreads();

    int cg = tid & 7;            // col group: cols [cg*4, cg*4+4)
    int np = tid >> 3;           // node pair 0..31
    int n0 = np * 2, n1 = n0 + 1;

    float4 a0 = z, a1 = z;
    #pragma unroll
    for (int k = 0; k < IN_DIM; k += 4) {
        float4 x0 = *(const float4*)&sX[n0 * IN_DIM + k];
        float4 x1 = *(const float4*)&sX[n1 * IN_DIM + k];
        float4 c0 = *(const float4*)&sW[(k + 0) * HID_DIM + cg * 4];
        float4 c1 = *(const float4*)&sW[(k + 1) * HID_DIM + cg * 4];
        float4 c2 = *(const float4*)&sW[(k + 2) * HID_DIM + cg * 4];
        float4 c3 = *(const float4*)&sW[(k + 3) * HID_DIM + cg * 4];
        fma4(a0, x0.x, c0); fma4(a0, x0.y, c1);
        fma4(a0, x0.z, c2); fma4(a0, x0.w, c3);
        fma4(a1, x1.x, c0); fma4(a1, x1.y, c1);
        fma4(a1, x1.z, c2); fma4(a1, x1.w, c3);
    }

    int gn0 = base + n0;
    int gn1 = base + n1;
    if (gn0 < N_NODES) {
        float nrm = rsqrtf(fmaxf((float)g_deg_out[gn0], 1.0f));
        a0.x *= nrm; a0.y *= nrm; a0.z *= nrm; a0.w *= nrm;
        ((float4*)&g_h[gn0 * HID_DIM])[cg] = a0;
    }
    if (gn1 < N_NODES) {
        float nrm = rsqrtf(fmaxf((float)g_deg_out[gn1], 1.0f));
        a1.x *= nrm; a1.y *= nrm; a1.z *= nrm; a1.w *= nrm;
        ((float4*)&g_h[gn1 * HID_DIM])[cg] = a1;
    }
}

// ---------------------------------------------------------------------------
// Scan step A: per-block sums of deg_in
__global__ __launch_bounds__(SCAN_CHUNK) void k_scanA() {
    __shared__ int s[SCAN_CHUNK];
    int t = threadIdx.x;
    int i = blockIdx.x * SCAN_CHUNK + t;
    s[t] = (i < N_NODES) ? g_deg_in[i] : 0;
    __syncthreads();
    #pragma unroll
    for (int o = SCAN_CHUNK / 2; o > 0; o >>= 1) {
        if (t < o) s[t] += s[t + o];
        __syncthreads();
    }
    if (t == 0) g_part[blockIdx.x] = s[0];
}

// Scan step B: exclusive scan of partials (single block)
__global__ __launch_bounds__(256) void k_scanB() {
    __shared__ int s[256];
    int t = threadIdx.x;
    int v = (t < SCAN_NBLK) ? g_part[t] : 0;
    s[t] = v;
    __syncthreads();
    #pragma unroll
    for (int o = 1; o < 256; o <<= 1) {
        int x = (t >= o) ? s[t - o] : 0;
        __syncthreads();
        s[t] += x;
        __syncthreads();
    }
    if (t < SCAN_NBLK) g_part[t] = s[t] - v;   // exclusive
}

// Scan step C: per-block exclusive scan + offset; writes g_off and g_cursor
__global__ __launch_bounds__(SCAN_CHUNK) void k_scanC() {
    __shared__ int s[SCAN_CHUNK];
    int t = threadIdx.x;
    int i = blockIdx.x * SCAN_CHUNK + t;
    int v = (i < N_NODES) ? g_deg_in[i] : 0;
    s[t] = v;
    __syncthreads();
    #pragma unroll
    for (int o = 1; o < SCAN_CHUNK; o <<= 1) {
        int x = (t >= o) ? s[t - o] : 0;
        __syncthreads();
        s[t] += x;
        __syncthreads();
    }
    if (i < N_NODES) {
        int off = s[t] - v + g_part[blockIdx.x];
        g_off[i] = off;
        g_cursor[i] = off;
    }
}

// ---------------------------------------------------------------------------
// Counting-sort bucket fill: group src ids by dst
__global__ void k_bucket(const int* __restrict__ src,
                         const int* __restrict__ dst) {
    int e = blockIdx.x * blockDim.x + threadIdx.x;
    if (e < N_EDGES) {
        int d = dst[e];
        int pos = atomicAdd(&g_cursor[d], 1);
        g_srclist[pos] = src[e];
    }
}

// ---------------------------------------------------------------------------
// Pull aggregation: one warp per node, lane = column. No atomics.
// Fuses finalize: out = relu(acc * norm_dst + b).
__global__ __launch_bounds__(256) void k_aggregate(float* __restrict__ out,
                                                   const float* __restrict__ b) {
    int gtid = blockIdx.x * blockDim.x + threadIdx.x;
    int v = gtid >> 5;
    int lane = gtid & 31;
    if (v >= N_NODES) return;

    int off0 = g_off[v];
    int off1 = (v < N_NODES - 1) ? g_off[v + 1] : N_EDGES;

    float acc = 0.0f;
    int i = off0;
    for (; i + 4 <= off1; i += 4) {
        int s0 = __ldg(&g_srclist[i + 0]);
        int s1 = __ldg(&g_srclist[i + 1]);
        int s2 = __ldg(&g_srclist[i + 2]);
        int s3 = __ldg(&g_srclist[i + 3]);
        float v0 = __ldg(&g_h[s0 * HID_DIM + lane]);
        float v1 = __ldg(&g_h[s1 * HID_DIM + lane]);
        float v2 = __ldg(&g_h[s2 * HID_DIM + lane]);
        float v3 = __ldg(&g_h[s3 * HID_DIM + lane]);
        acc += v0 + v1 + v2 + v3;
    }
    for (; i < off1; i++) {
        acc += __ldg(&g_h[__ldg(&g_srclist[i]) * HID_DIM + lane]);
    }

    float deg = (float)(off1 - off0);
    float nrm = rsqrtf(fmaxf(deg, 1.0f));
    float r = acc * nrm + __ldg(&b[lane]);
    out[v * HID_DIM + lane] = fmaxf(r, 0.0f);
}

// ---------------------------------------------------------------------------
extern "C" void kernel_launch(void* const* d_in, const int* in_sizes, int n_in,
                              void* d_out, int out_size) {
    const float* features = (const float*)d_in[0];
    const int*   src      = (const int*)d_in[1];
    const int*   dst      = (const int*)d_in[2];
    const float* W        = (const float*)d_in[3];
    const float* b        = (const float*)d_in[4];
    float* out = (float*)d_out;

    k_zero<<<256, 256>>>();
    k_degrees<<<(N_EDGES + 255) / 256, 256>>>(src, dst);
    k_gemm<<<(N_NODES + 63) / 64, 256>>>(features, W);

    k_scanA<<<SCAN_NBLK, SCAN_CHUNK>>>();
    k_scanB<<<1, 256>>>();
    k_scanC<<<SCAN_NBLK, SCAN_CHUNK>>>();

    k_bucket<<<(N_EDGES + 255) / 256, 256>>>(src, dst);

    long long agg_threads = (long long)N_NODES * 32;
    k_aggregate<<<(int)((agg_threads + 255) / 256), 256>>>(out, b);
}